// round 15
// baseline (speedup 1.0000x reference)
#include <cuda_runtime.h>
#include <cuda_fp16.h>
#include <cstdint>

// Problem constants (fixed by the reference)
#define BATCH   50000
#define KNEI    32
#define FDIM    256     // feature dim; 2F = 512 = GEMM K
#define NNODES  200000
#define NOUT    256

// fp16 copy of the feature table [NNODES, FDIM] (rebuilt every call)
__device__ __half g_feats_h[(size_t)NNODES * FDIM];
// fp16 concatenated GEMM A matrix: [BATCH][512] = [x_self_f16 | x_neigh_f16]
__device__ __half g_h[(size_t)BATCH * 2 * FDIM];
// fp16 transposed weights: W_t[n][k], n in [0,256), k in [0,512)
__device__ __half g_W_t[(size_t)NOUT * 2 * FDIM];
// per-m-tile gather completion counters (zeroed by convert_kernel each call)
#define NGROUP 391
__device__ int g_cnt[NGROUP];

#define FEATS_BLOCKS ((NNODES * FDIM) / (256 * 8))   // 25000
#define XSELF_BLOCKS ((BATCH * FDIM) / (256 * 8))    // 6250
#define W_BLOCKS     ((2 * FDIM / 32) * (NOUT / 32)) // 128
#define NGATHER      (BATCH / 8)                     // 6250
#define NGEMM        (NGROUP * 4)                    // 1564
#define FUSED_BLOCKS (NGEMM * 4)                     // 6256 (>= NGATHER)

// ---------------------------------------------------------------------------
// Kernel 1: fp32 -> fp16 conversions (feats, x_self, W transpose) + counter
// zeroing.  HBM-streaming floor (~53us).  Must NOT overlap the gather
// (both LTS-bound — measured rounds 9 & 11).
// ---------------------------------------------------------------------------
__global__ void convert_kernel(const float4* __restrict__ feats4,
                               const float4* __restrict__ xself4,
                               const float* __restrict__ W) {
    const int bid = blockIdx.x;
    if (bid < FEATS_BLOCKS) {
        const long long t = (long long)bid * 256 + threadIdx.x;
        const float4 a = feats4[2 * t];
        const float4 b = feats4[2 * t + 1];
        __half2 o[4];
        o[0] = __floats2half2_rn(a.x, a.y);
        o[1] = __floats2half2_rn(a.z, a.w);
        o[2] = __floats2half2_rn(b.x, b.y);
        o[3] = __floats2half2_rn(b.z, b.w);
        *reinterpret_cast<uint4*>(g_feats_h + t * 8) = *reinterpret_cast<uint4*>(o);
    } else if (bid < FEATS_BLOCKS + XSELF_BLOCKS) {
        const long long e = (long long)(bid - FEATS_BLOCKS) * 256 + threadIdx.x;
        const float4 a = xself4[2 * e];
        const float4 b = xself4[2 * e + 1];
        __half2 o[4];
        o[0] = __floats2half2_rn(a.x, a.y);
        o[1] = __floats2half2_rn(a.z, a.w);
        o[2] = __floats2half2_rn(b.x, b.y);
        o[3] = __floats2half2_rn(b.z, b.w);
        const long long row = e / 32;          // 32 * 8 halves = 256 per row
        const long long col = (e % 32) * 8;
        *reinterpret_cast<uint4*>(g_h + row * (2 * FDIM) + col) =
            *reinterpret_cast<uint4*>(o);
    } else if (bid < FEATS_BLOCKS + XSELF_BLOCKS + W_BLOCKS) {
        // W transpose: 32x32 fp32 tile -> fp16 W_t
        __shared__ float tile[32][33];
        const int b2 = bid - FEATS_BLOCKS - XSELF_BLOCKS;
        const int k0 = (b2 & 15) * 32;      // 16 k-blocks
        const int n0 = (b2 >> 4) * 32;      // 8 n-blocks
        const int tx = threadIdx.x & 31;
        const int ty = threadIdx.x >> 5;    // 0..7
#pragma unroll
        for (int j = 0; j < 4; j++)
            tile[ty + j * 8][tx] = W[(long long)(k0 + ty + j * 8) * NOUT + n0 + tx];
        __syncthreads();
#pragma unroll
        for (int j = 0; j < 4; j++) {
            const int n = ty + j * 8;
            g_W_t[(long long)(n0 + n) * (2 * FDIM) + k0 + tx] =
                __float2half(tile[tx][n]);
        }
    } else {
        // zero the gather-group counters for this call
        if (threadIdx.x < NGROUP) g_cnt[threadIdx.x] = 0;
    }
}

// ---------------------------------------------------------------------------
// Fused kernel 2: gather + dependency-gated GEMM.
//   CTA c: gather block c (rows 8c..8c+7 of x_neigh) — unconditional,
//   so counter progress never depends on CTA scheduling (no deadlock).
//   CTAs with (c&3)==3 then run GEMM tile q=c>>2 (m=q>>2, n=q&3) after
//   spinning on g_cnt[m] (group m = gather blocks [16m,16m+16) = the CTA's
//   own neighborhood of bids).  Gather is LTS-bound, GEMM smem/tensor-bound
//   -> true overlap.
// GEMM: BM=128, BN=64, BK=32, 4-stage cp.async, full K=512, one barrier per
// stage, fully unrolled (round-13 proven body).
// ---------------------------------------------------------------------------
#define BM 128
#define BN 64
#define BK 32
#define STAGES 4
#define A_TILE_B (BM * BK * 2)            // 8192
#define B_TILE_B (BN * BK * 2)            // 4096
#define STAGE_B  (A_TILE_B + B_TILE_B)    // 12288

__device__ __forceinline__ unsigned swz(unsigned off) {
    return off ^ (((off >> 7) & 7u) << 4);
}

__device__ __forceinline__ void mma_f16(float& d0, float& d1, float& d2, float& d3,
                                        unsigned a0, unsigned a1, unsigned a2, unsigned a3,
                                        unsigned b0, unsigned b1) {
    asm volatile(
        "mma.sync.aligned.m16n8k16.row.col.f32.f16.f16.f32 "
        "{%0,%1,%2,%3}, {%4,%5,%6,%7}, {%8,%9}, {%0,%1,%2,%3};"
        : "+f"(d0), "+f"(d1), "+f"(d2), "+f"(d3)
        : "r"(a0), "r"(a1), "r"(a2), "r"(a3), "r"(b0), "r"(b1));
}

__device__ __forceinline__ void ldmatrix_x4(unsigned& r0, unsigned& r1,
                                            unsigned& r2, unsigned& r3,
                                            unsigned saddr) {
    asm volatile("ldmatrix.sync.aligned.m8n8.x4.shared.b16 {%0,%1,%2,%3}, [%4];"
                 : "=r"(r0), "=r"(r1), "=r"(r2), "=r"(r3) : "r"(saddr));
}

__device__ __forceinline__ void cp_async16(unsigned dst, const void* src, int sz) {
    asm volatile("cp.async.cg.shared.global [%0], [%1], 16, %2;\n"
                 :: "r"(dst), "l"(src), "r"(sz));
}
__device__ __forceinline__ void cp_commit() {
    asm volatile("cp.async.commit_group;\n");
}
template <int N>
__device__ __forceinline__ void cp_wait() {
    asm volatile("cp.async.wait_group %0;\n" :: "n"(N));
}

__device__ __forceinline__ int ld_acquire(const int* p) {
    int v;
    asm volatile("ld.acquire.gpu.global.b32 %0, [%1];" : "=r"(v) : "l"(p));
    return v;
}

__global__ __launch_bounds__(256, 4)
void fused_gather_gemm_kernel(const void* __restrict__ idx_raw,
                              const float* __restrict__ bias,
                              float* __restrict__ out,
                              int M) {
    __shared__ __align__(16) char smem[STAGES * STAGE_B];   // 48 KB (union)

    const int c    = blockIdx.x;
    const int tid  = threadIdx.x;
    const int warp = tid >> 5;
    const int lane = tid & 31;

    // ===================== phase 1: gather block c ==========================
    if (c < NGATHER) {
        int hi_zero = 1;
        if (tid < 128) {
            const uint2 probe = reinterpret_cast<const uint2*>(idx_raw)[tid];
            hi_zero = (probe.y == 0u);
        }
        const int is64 = __syncthreads_and(hi_zero);

        int* sidx = reinterpret_cast<int*>(smem);
        const long long flat = (long long)c * 256 + tid;
        int v;
        if (is64) v = (int)reinterpret_cast<const long long*>(idx_raw)[flat];
        else      v = reinterpret_cast<const int*>(idx_raw)[flat];
        sidx[tid] = v;
        __syncthreads();

        const int row = c * 8 + warp;

        float acc[8];
#pragma unroll
        for (int j = 0; j < 8; j++) acc[j] = 0.f;

#pragma unroll
        for (int k = 0; k < KNEI; k++) {
            const long long node = sidx[warp * KNEI + k];
            const uint4 raw = *reinterpret_cast<const uint4*>(
                g_feats_h + node * FDIM + lane * 8);
            const __half2* h = reinterpret_cast<const __half2*>(&raw);
#pragma unroll
            for (int j = 0; j < 4; j++) {
                const float2 f = __half22float2(h[j]);
                acc[2 * j]     += f.x;
                acc[2 * j + 1] += f.y;
            }
        }
        const float s = 1.0f / (float)KNEI;
        __half2 o[4];
#pragma unroll
        for (int j = 0; j < 4; j++)
            o[j] = __floats2half2_rn(acc[2 * j] * s, acc[2 * j + 1] * s);
        *reinterpret_cast<uint4*>(g_h + (long long)row * (2 * FDIM) + FDIM + lane * 8) =
            *reinterpret_cast<uint4*>(o);

        // publish: all 256 threads' writes -> barrier -> fence -> release count
        __syncthreads();
        if (tid == 0) {
            __threadfence();
            atomicAdd(&g_cnt[c >> 4], 1);
        }
    }

    // ===================== phase 2: GEMM tile (1 in 4 CTAs) =================
    if ((c & 3) != 3) return;
    const int q  = c >> 2;            // 0..1563
    const int mt = q >> 2;            // m-tile 0..390
    const int nt = q & 3;             // n-tile 0..3
    const int bm = mt * BM;
    const int bn = nt * BN;

    // wait for gather group mt (its blocks are this CTA's bid neighborhood)
    const int target = (NGATHER - 16 * mt) < 16 ? (NGATHER - 16 * mt) : 16;
    if (tid == 0) {
        while (ld_acquire(&g_cnt[mt]) < target) __nanosleep(200);
    }
    __syncthreads();

    const int wm  = warp >> 1;        // 0..3
    const int wn  = warp & 1;         // 0..1
    const int gid = lane >> 2;        // 0..7
    const int tig = lane & 3;         // 0..3

    const unsigned sbase = (unsigned)__cvta_generic_to_shared(smem);

    // stage-invariant cp.async mapping (hoisted)
    const int gr  = tid >> 2;          // 0..63
    const int gg  = tid & 3;           // 0..3
    const unsigned soffA0 = swz((unsigned)(gr * 64 + gg * 16));
    const unsigned soffA1 = swz((unsigned)((gr + 64) * 64 + gg * 16));
    const unsigned soffB  = soffA0;
    const int mA0 = bm + gr;
    const int mA1 = bm + gr + 64;
    const int szA0 = (mA0 < M) ? 16 : 0;
    const int szA1 = (mA1 < M) ? 16 : 0;
    const __half* pA0 = g_h   + (long long)mA0 * (2 * FDIM) + gg * 8;
    const __half* pA1 = g_h   + (long long)mA1 * (2 * FDIM) + gg * 8;
    const __half* pB  = g_W_t + (long long)(bn + gr) * (2 * FDIM) + gg * 8;

    // A fragment ldmatrix lane addressing
    const int lm_tile = lane >> 3;
    const int lm_row  = (lane & 7) + (lm_tile & 1) * 8;
    const int lm_koff = (lm_tile >> 1) * 8;
    // B fragment ldmatrix lane addressing
    const int bn_row  = ((lane >> 4) & 1) * 8 + (lane & 7);
    const int bk_add  = ((lane >> 3) & 1) * 8;

    float acc[2][4][4];
#pragma unroll
    for (int i = 0; i < 2; i++)
#pragma unroll
        for (int j = 0; j < 4; j++)
#pragma unroll
            for (int p = 0; p < 4; p++) acc[i][j][p] = 0.f;

#define ISSUE_STAGE(s, buf)                                                     \
    {                                                                           \
        const unsigned abase = sbase + (buf) * STAGE_B;                         \
        cp_async16(abase + soffA0, pA0 + (s) * BK, szA0);                       \
        cp_async16(abase + soffA1, pA1 + (s) * BK, szA1);                       \
        cp_async16(abase + A_TILE_B + soffB, pB + (s) * BK, 16);                \
        cp_commit();                                                            \
    }

    ISSUE_STAGE(0, 0)
    ISSUE_STAGE(1, 1)
    ISSUE_STAGE(2, 2)

    const int NSTAGE = (2 * FDIM) / BK;   // 16

#pragma unroll
    for (int s = 0; s < NSTAGE; s++) {
        if (s < NSTAGE - 2)       cp_wait<2>();
        else if (s == NSTAGE - 2) cp_wait<1>();
        else                      cp_wait<0>();
        __syncthreads();

        if (s + 3 < NSTAGE) {
            ISSUE_STAGE(s + 3, (s + 3) % STAGES)
        }

        const unsigned abase = sbase + (s % STAGES) * STAGE_B;
        const unsigned bbase = abase + A_TILE_B;

#pragma unroll
        for (int ks = 0; ks < 2; ks++) {
            const int kk = ks * 16;
            unsigned af[2][4];
#pragma unroll
            for (int mi = 0; mi < 2; mi++) {
                const int r = wm * 32 + mi * 16 + lm_row;
                const unsigned sa = abase + swz((unsigned)(r * 64 + (kk + lm_koff) * 2));
                ldmatrix_x4(af[mi][0], af[mi][1], af[mi][2], af[mi][3], sa);
            }
            unsigned bf[4][2];
#pragma unroll
            for (int nj2 = 0; nj2 < 2; nj2++) {
                const int n = wn * 32 + nj2 * 16 + bn_row;
                const unsigned sb = bbase + swz((unsigned)(n * 64 + (kk + bk_add) * 2));
                unsigned r0, r1, r2, r3;
                ldmatrix_x4(r0, r1, r2, r3, sb);
                bf[2 * nj2][0]     = r0; bf[2 * nj2][1]     = r1;
                bf[2 * nj2 + 1][0] = r2; bf[2 * nj2 + 1][1] = r3;
            }
#pragma unroll
            for (int nj = 0; nj < 4; nj++) {
                mma_f16(acc[0][nj][0], acc[0][nj][1], acc[0][nj][2], acc[0][nj][3],
                        af[0][0], af[0][1], af[0][2], af[0][3], bf[nj][0], bf[nj][1]);
                mma_f16(acc[1][nj][0], acc[1][nj][1], acc[1][nj][2], acc[1][nj][3],
                        af[1][0], af[1][1], af[1][2], af[1][3], bf[nj][0], bf[nj][1]);
            }
        }
    }

    // epilogue: bias + store
#pragma unroll
    for (int mi = 0; mi < 2; mi++) {
        const int m0 = bm + wm * 32 + mi * 16 + gid;
#pragma unroll
        for (int nj = 0; nj < 4; nj++) {
            const int n = bn + wn * 32 + nj * 8 + 2 * tig;
            const float b0 = bias[n];
            const float b1 = bias[n + 1];
            if (m0 < M) {
                float2 v = make_float2(acc[mi][nj][0] + b0, acc[mi][nj][1] + b1);
                *reinterpret_cast<float2*>(out + (long long)m0 * NOUT + n) = v;
            }
            if (m0 + 8 < M) {
                float2 v = make_float2(acc[mi][nj][2] + b0, acc[mi][nj][3] + b1);
                *reinterpret_cast<float2*>(out + (long long)(m0 + 8) * NOUT + n) = v;
            }
        }
    }
#undef ISSUE_STAGE
}

// ---------------------------------------------------------------------------
// Launch
// Inputs: x_self[f32 B*F], feats[f32 N*F], neigh_idx[B*K], W[f32 512*256], b[f32 256]
// ---------------------------------------------------------------------------
extern "C" void kernel_launch(void* const* d_in, const int* in_sizes, int n_in,
                              void* d_out, int out_size) {
    const float4* xself4 = (const float4*)d_in[0];
    const float4* feats4 = (const float4*)d_in[1];
    const void*   nidx   = d_in[2];
    const float*  W      = (const float*)d_in[3];
    const float*  bias   = (const float*)d_in[4];
    float*        out    = (float*)d_out;

    (void)in_sizes; (void)n_in; (void)out_size;

    // 1) fp32 -> fp16: feats, x_self, W transpose + counter zeroing
    convert_kernel<<<FEATS_BLOCKS + XSELF_BLOCKS + W_BLOCKS + 1, 256>>>(
        feats4, xself4, W);

    // 2) fused gather + dependency-gated GEMM
    fused_gather_gemm_kernel<<<FUSED_BLOCKS, 256>>>(nidx, bias, out, BATCH);
}

// round 16
// speedup vs baseline: 1.0198x; 1.0198x over previous
#include <cuda_runtime.h>
#include <cuda_fp16.h>
#include <cstdint>

// Problem constants (fixed by the reference)
#define BATCH   50000
#define KNEI    32
#define FDIM    256     // feature dim; 2F = 512 = GEMM K
#define NNODES  200000
#define NOUT    256

// fp16 copy of the feature table [NNODES, FDIM] (rebuilt every call)
__device__ __half g_feats_h[(size_t)NNODES * FDIM];
// fp16 concatenated GEMM A matrix: [BATCH][512] = [x_self_f16 | x_neigh_f16]
__device__ __half g_h[(size_t)BATCH * 2 * FDIM];
// fp16 transposed weights: W_t[n][k], n in [0,256), k in [0,512)
__device__ __half g_W_t[(size_t)NOUT * 2 * FDIM];

// 16 floats per thread
#define FEATS_BLOCKS ((NNODES * FDIM) / (256 * 16))  // 12500
#define XSELF_BLOCKS ((BATCH * FDIM) / (256 * 16))   // 3125
#define W_BLOCKS     ((2 * FDIM / 32) * (NOUT / 32)) // 128

// ---------------------------------------------------------------------------
// Kernel 1: fp32 -> fp16 conversions: feats table, x_self (left half of g_h),
// and W transpose -> W_t.  One streaming launch.  16 floats/thread
// (4 float4 loads in flight) to push HBM utilization above 82%.
// NOTE: do NOT interleave any of this with the gather — both phases bottleneck
// the LTS port, so interleaving gives zero overlap (measured, rounds 9/11/14).
// ---------------------------------------------------------------------------
__global__ void convert_kernel(const float4* __restrict__ feats4,
                               const float4* __restrict__ xself4,
                               const float* __restrict__ W) {
    const int bid = blockIdx.x;
    if (bid < FEATS_BLOCKS) {
        const long long t = (long long)bid * 256 + threadIdx.x;
        float4 a0 = feats4[4 * t];
        float4 a1 = feats4[4 * t + 1];
        float4 a2 = feats4[4 * t + 2];
        float4 a3 = feats4[4 * t + 3];
        __half2 o[8];
        o[0] = __floats2half2_rn(a0.x, a0.y);
        o[1] = __floats2half2_rn(a0.z, a0.w);
        o[2] = __floats2half2_rn(a1.x, a1.y);
        o[3] = __floats2half2_rn(a1.z, a1.w);
        o[4] = __floats2half2_rn(a2.x, a2.y);
        o[5] = __floats2half2_rn(a2.z, a2.w);
        o[6] = __floats2half2_rn(a3.x, a3.y);
        o[7] = __floats2half2_rn(a3.z, a3.w);
        uint4* dst = reinterpret_cast<uint4*>(g_feats_h + t * 16);
        dst[0] = reinterpret_cast<uint4*>(o)[0];
        dst[1] = reinterpret_cast<uint4*>(o)[1];
    } else if (bid < FEATS_BLOCKS + XSELF_BLOCKS) {
        const long long e = (long long)(bid - FEATS_BLOCKS) * 256 + threadIdx.x;
        float4 a0 = xself4[4 * e];
        float4 a1 = xself4[4 * e + 1];
        float4 a2 = xself4[4 * e + 2];
        float4 a3 = xself4[4 * e + 3];
        __half2 o[8];
        o[0] = __floats2half2_rn(a0.x, a0.y);
        o[1] = __floats2half2_rn(a0.z, a0.w);
        o[2] = __floats2half2_rn(a1.x, a1.y);
        o[3] = __floats2half2_rn(a1.z, a1.w);
        o[4] = __floats2half2_rn(a2.x, a2.y);
        o[5] = __floats2half2_rn(a2.z, a2.w);
        o[6] = __floats2half2_rn(a3.x, a3.y);
        o[7] = __floats2half2_rn(a3.z, a3.w);
        // 16 floats per thread; row = 256 floats -> 16 threads per row
        const long long row = e >> 4;
        const long long col = (e & 15) * 16;
        uint4* dst = reinterpret_cast<uint4*>(g_h + row * (2 * FDIM) + col);
        dst[0] = reinterpret_cast<uint4*>(o)[0];
        dst[1] = reinterpret_cast<uint4*>(o)[1];
    } else {
        // W transpose: 32x32 fp32 tile -> fp16 W_t
        __shared__ float tile[32][33];
        const int b2 = bid - FEATS_BLOCKS - XSELF_BLOCKS;
        const int k0 = (b2 & 15) * 32;      // 16 k-blocks
        const int n0 = (b2 >> 4) * 32;      // 8 n-blocks
        const int tx = threadIdx.x & 31;
        const int ty = threadIdx.x >> 5;    // 0..7
#pragma unroll
        for (int j = 0; j < 4; j++)
            tile[ty + j * 8][tx] = W[(long long)(k0 + ty + j * 8) * NOUT + n0 + tx];
        __syncthreads();
#pragma unroll
        for (int j = 0; j < 4; j++) {
            const int n = ty + j * 8;
            g_W_t[(long long)(n0 + n) * (2 * FDIM) + k0 + tx] =
                __float2half(tile[tx][n]);
        }
    }
}

// ---------------------------------------------------------------------------
// Kernel 2: gather + mean from fp16 table, fp32 accumulate, fp16 out into
// the right half (cols 256..511) of g_h.  8 rows/block, 1 warp per row.
// At the LTS-port floor (~820MB of L2 reads).  Index dtype (int32 vs int64)
// detected per-block: int64 indices < 200000 have all-zero hi words.
// ---------------------------------------------------------------------------
__global__ void gather_mean_kernel(const void* __restrict__ idx_raw) {
    const int tid  = threadIdx.x;
    const int warp = tid >> 5;
    const int lane = tid & 31;

    int hi_zero = 1;
    if (tid < 128) {
        const uint2 probe = reinterpret_cast<const uint2*>(idx_raw)[tid];
        hi_zero = (probe.y == 0u);
    }
    const int is64 = __syncthreads_and(hi_zero);

    __shared__ int sidx[256];
    const long long flat = (long long)blockIdx.x * 256 + tid;
    int v;
    if (is64) v = (int)reinterpret_cast<const long long*>(idx_raw)[flat];
    else      v = reinterpret_cast<const int*>(idx_raw)[flat];
    sidx[tid] = v;
    __syncthreads();

    const int row = blockIdx.x * 8 + warp;

    float acc[8];
#pragma unroll
    for (int j = 0; j < 8; j++) acc[j] = 0.f;

#pragma unroll
    for (int k = 0; k < KNEI; k++) {
        const long long node = sidx[warp * KNEI + k];
        const uint4 raw = *reinterpret_cast<const uint4*>(
            g_feats_h + node * FDIM + lane * 8);
        const __half2* h = reinterpret_cast<const __half2*>(&raw);
#pragma unroll
        for (int j = 0; j < 4; j++) {
            const float2 f = __half22float2(h[j]);
            acc[2 * j]     += f.x;
            acc[2 * j + 1] += f.y;
        }
    }
    const float s = 1.0f / (float)KNEI;
    __half2 o[4];
#pragma unroll
    for (int j = 0; j < 4; j++)
        o[j] = __floats2half2_rn(acc[2 * j] * s, acc[2 * j + 1] * s);
    *reinterpret_cast<uint4*>(g_h + (long long)row * (2 * FDIM) + FDIM + lane * 8) =
        *reinterpret_cast<uint4*>(o);
}

// ---------------------------------------------------------------------------
// Kernel 3: fp16 tensor-core GEMM, 4-stage cp.async pipeline.
//   out[M,256] = g_h[M,512] @ W_t^T + bias
// BM=128, BN=64, BK=32, STAGES=4 (48KB smem, 4 CTAs/SM).  8 warps:
// 4 in M x 2 in N, warp tile 32x32 -> 32 fp32 accs/thread (regs <= 64).
// ONE barrier per stage; stage loop fully unrolled; gmem pointers
// strength-reduced.  (Round-13 proven body, best measured config.)
// Grid: x = n-tile (4), y = m-tile (391).
// ---------------------------------------------------------------------------
#define BM 128
#define BN 64
#define BK 32
#define STAGES 4
#define A_TILE_B (BM * BK * 2)            // 8192
#define B_TILE_B (BN * BK * 2)            // 4096
#define STAGE_B  (A_TILE_B + B_TILE_B)    // 12288

__device__ __forceinline__ unsigned swz(unsigned off) {
    return off ^ (((off >> 7) & 7u) << 4);
}

__device__ __forceinline__ void mma_f16(float& d0, float& d1, float& d2, float& d3,
                                        unsigned a0, unsigned a1, unsigned a2, unsigned a3,
                                        unsigned b0, unsigned b1) {
    asm volatile(
        "mma.sync.aligned.m16n8k16.row.col.f32.f16.f16.f32 "
        "{%0,%1,%2,%3}, {%4,%5,%6,%7}, {%8,%9}, {%0,%1,%2,%3};"
        : "+f"(d0), "+f"(d1), "+f"(d2), "+f"(d3)
        : "r"(a0), "r"(a1), "r"(a2), "r"(a3), "r"(b0), "r"(b1));
}

__device__ __forceinline__ void ldmatrix_x4(unsigned& r0, unsigned& r1,
                                            unsigned& r2, unsigned& r3,
                                            unsigned saddr) {
    asm volatile("ldmatrix.sync.aligned.m8n8.x4.shared.b16 {%0,%1,%2,%3}, [%4];"
                 : "=r"(r0), "=r"(r1), "=r"(r2), "=r"(r3) : "r"(saddr));
}

__device__ __forceinline__ void cp_async16(unsigned dst, const void* src, int sz) {
    asm volatile("cp.async.cg.shared.global [%0], [%1], 16, %2;\n"
                 :: "r"(dst), "l"(src), "r"(sz));
}
__device__ __forceinline__ void cp_commit() {
    asm volatile("cp.async.commit_group;\n");
}
template <int N>
__device__ __forceinline__ void cp_wait() {
    asm volatile("cp.async.wait_group %0;\n" :: "n"(N));
}

__global__ __launch_bounds__(256, 4)
void gemm_f16_pipe_kernel(const float* __restrict__ bias,
                          float* __restrict__ out,
                          int M) {
    __shared__ __align__(16) char smem[STAGES * STAGE_B];   // 48 KB

    const int bm  = blockIdx.y * BM;
    const int bn  = blockIdx.x * BN;
    const int tid = threadIdx.x;

    const int warp = tid >> 5;
    const int lane = tid & 31;
    const int wm   = warp >> 1;        // 0..3
    const int wn   = warp & 1;         // 0..1
    const int gid  = lane >> 2;        // 0..7
    const int tig  = lane & 3;         // 0..3

    const unsigned sbase = (unsigned)__cvta_generic_to_shared(smem);

    // ---- stage-invariant cp.async mapping (hoisted) ----
    const int gr  = tid >> 2;          // 0..63
    const int gg  = tid & 3;           // 0..3
    const unsigned soffA0 = swz((unsigned)(gr * 64 + gg * 16));
    const unsigned soffA1 = swz((unsigned)((gr + 64) * 64 + gg * 16));
    const unsigned soffB  = soffA0;
    const int mA0 = bm + gr;
    const int mA1 = bm + gr + 64;
    const int szA0 = (mA0 < M) ? 16 : 0;
    const int szA1 = (mA1 < M) ? 16 : 0;
    const __half* pA0 = g_h   + (long long)mA0 * (2 * FDIM) + gg * 8;
    const __half* pA1 = g_h   + (long long)mA1 * (2 * FDIM) + gg * 8;
    const __half* pB  = g_W_t + (long long)(bn + gr) * (2 * FDIM) + gg * 8;

    // A fragment ldmatrix lane addressing
    const int lm_tile = lane >> 3;
    const int lm_row  = (lane & 7) + (lm_tile & 1) * 8;
    const int lm_koff = (lm_tile >> 1) * 8;
    // B fragment ldmatrix lane addressing (non-trans over [n][k] rows)
    const int bn_row  = ((lane >> 4) & 1) * 8 + (lane & 7);
    const int bk_add  = ((lane >> 3) & 1) * 8;

    float acc[2][4][4];
#pragma unroll
    for (int i = 0; i < 2; i++)
#pragma unroll
        for (int j = 0; j < 4; j++)
#pragma unroll
            for (int q = 0; q < 4; q++) acc[i][j][q] = 0.f;

#define ISSUE_STAGE(s, buf)                                                     \
    {                                                                           \
        const unsigned abase = sbase + (buf) * STAGE_B;                         \
        cp_async16(abase + soffA0, pA0 + (s) * BK, szA0);                       \
        cp_async16(abase + soffA1, pA1 + (s) * BK, szA1);                       \
        cp_async16(abase + A_TILE_B + soffB, pB + (s) * BK, 16);                \
        cp_commit();                                                            \
    }

    // ---- prologue: issue stages 0,1,2 ----
    ISSUE_STAGE(0, 0)
    ISSUE_STAGE(1, 1)
    ISSUE_STAGE(2, 2)

    const int NSTAGE = (2 * FDIM) / BK;   // 16

#pragma unroll
    for (int s = 0; s < NSTAGE; s++) {
        if (s < NSTAGE - 2)       cp_wait<2>();
        else if (s == NSTAGE - 2) cp_wait<1>();
        else                      cp_wait<0>();
        // Single barrier per stage: orders (a) everyone's cp_wait for the
        // buffer consumed this stage, and (b) everyone's compute(s-1) before
        // issue(s+3) overwrites buffer (s-1)%4.
        __syncthreads();

        if (s + 3 < NSTAGE) {
            ISSUE_STAGE(s + 3, (s + 3) % STAGES)
        }

        // compute stage s from buffer s%4
        const unsigned abase = sbase + (s % STAGES) * STAGE_B;
        const unsigned bbase = abase + A_TILE_B;

#pragma unroll
        for (int ks = 0; ks < 2; ks++) {
            const int kk = ks * 16;
            unsigned af[2][4];
#pragma unroll
            for (int mi = 0; mi < 2; mi++) {
                const int r = wm * 32 + mi * 16 + lm_row;
                const unsigned sa = abase + swz((unsigned)(r * 64 + (kk + lm_koff) * 2));
                ldmatrix_x4(af[mi][0], af[mi][1], af[mi][2], af[mi][3], sa);
            }
            unsigned bf[4][2];
#pragma unroll
            for (int nj2 = 0; nj2 < 2; nj2++) {
                const int n = wn * 32 + nj2 * 16 + bn_row;
                const unsigned sb = bbase + swz((unsigned)(n * 64 + (kk + bk_add) * 2));
                unsigned r0, r1, r2, r3;
                ldmatrix_x4(r0, r1, r2, r3, sb);
                bf[2 * nj2][0]     = r0; bf[2 * nj2][1]     = r1;
                bf[2 * nj2 + 1][0] = r2; bf[2 * nj2 + 1][1] = r3;
            }
#pragma unroll
            for (int nj = 0; nj < 4; nj++) {
                mma_f16(acc[0][nj][0], acc[0][nj][1], acc[0][nj][2], acc[0][nj][3],
                        af[0][0], af[0][1], af[0][2], af[0][3], bf[nj][0], bf[nj][1]);
                mma_f16(acc[1][nj][0], acc[1][nj][1], acc[1][nj][2], acc[1][nj][3],
                        af[1][0], af[1][1], af[1][2], af[1][3], bf[nj][0], bf[nj][1]);
            }
        }
        // no trailing barrier: next iteration's leading barrier provides the
        // required ordering before any buffer reuse.
    }

    // ---- epilogue: bias + store (c0,c1 contiguous -> float2) ----
#pragma unroll
    for (int mi = 0; mi < 2; mi++) {
        const int m0 = bm + wm * 32 + mi * 16 + gid;
#pragma unroll
        for (int nj = 0; nj < 4; nj++) {
            const int n = bn + wn * 32 + nj * 8 + 2 * tig;
            const float b0 = bias[n];
            const float b1 = bias[n + 1];
            if (m0 < M) {
                float2 v = make_float2(acc[mi][nj][0] + b0, acc[mi][nj][1] + b1);
                *reinterpret_cast<float2*>(out + (long long)m0 * NOUT + n) = v;
            }
            if (m0 + 8 < M) {
                float2 v = make_float2(acc[mi][nj][2] + b0, acc[mi][nj][3] + b1);
                *reinterpret_cast<float2*>(out + (long long)(m0 + 8) * NOUT + n) = v;
            }
        }
    }
#undef ISSUE_STAGE
}

// ---------------------------------------------------------------------------
// Launch
// Inputs: x_self[f32 B*F], feats[f32 N*F], neigh_idx[B*K], W[f32 512*256], b[f32 256]
// ---------------------------------------------------------------------------
extern "C" void kernel_launch(void* const* d_in, const int* in_sizes, int n_in,
                              void* d_out, int out_size) {
    const float4* xself4 = (const float4*)d_in[0];
    const float4* feats4 = (const float4*)d_in[1];
    const void*   nidx   = d_in[2];
    const float*  W      = (const float*)d_in[3];
    const float*  bias   = (const float*)d_in[4];
    float*        out    = (float*)d_out;

    (void)in_sizes; (void)n_in; (void)out_size;

    // 1) fp32 -> fp16: feature table, x_self, W transpose (one launch)
    convert_kernel<<<FEATS_BLOCKS + XSELF_BLOCKS + W_BLOCKS, 256>>>(
        feats4, xself4, W);

    // 2) gather + mean -> right half of g_h
    gather_mean_kernel<<<BATCH / 8, 256>>>(nidx);

    // 3) fp16 tensor-core GEMM (grid: x = n-tiles, y = m-tiles)
    dim3 grid(NOUT / BN, (BATCH + BM - 1) / BM);
    gemm_f16_pipe_kernel<<<grid, 256>>>(bias, out, BATCH);
}